// round 2
// baseline (speedup 1.0000x reference)
#include <cuda_runtime.h>
#include <cuda_bf16.h>

#define S_LEN 4096
#define HID   2048
#define QKV_LD 3072
#define WIN_  1024
#define SCALE_F 0.08838834764831845f   // 128^-0.5

static __device__ float g_qkv [S_LEN * QKV_LD];   // [s][ q(16*128) | k(4*128) | v(4*128) ]
static __device__ float g_attn[S_LEN * HID];

// ============================================================================
// GEMM:  C[M,N] = A[M,K] * B[N,K]^T     (both row-major, K contiguous)
// 128x128 block tile, BK=16, 256 threads, 8x8 microtile (split 4+4 pattern)
// Grid: (N/128, M/128)
// ============================================================================
__global__ __launch_bounds__(256)
void gemm_abt(const float* __restrict__ A, int lda,
              const float* __restrict__ B, int ldb,
              float* __restrict__ C, int ldc,
              int K)
{
    __shared__ float As[16][132];
    __shared__ float Bs[16][132];

    const int bm = blockIdx.y * 128;
    const int bn = blockIdx.x * 128;
    const int tid = threadIdx.x;
    const int ty = tid >> 4;      // 0..15
    const int tx = tid & 15;      // 0..15

    float acc[8][8];
    #pragma unroll
    for (int i = 0; i < 8; i++)
        #pragma unroll
        for (int j = 0; j < 8; j++) acc[i][j] = 0.f;

    const int lr = tid >> 2;            // 0..63  (load row)
    const int lc = (tid & 3) << 2;      // 0,4,8,12 (load col base)
    const float* Ap = A + (bm + lr) * lda + lc;
    const float* Bp = B + (bn + lr) * ldb + lc;

    for (int k0 = 0; k0 < K; k0 += 16) {
        float4 a0 = *(const float4*)(Ap + k0);
        float4 a1 = *(const float4*)(Ap + 64 * lda + k0);
        float4 b0 = *(const float4*)(Bp + k0);
        float4 b1 = *(const float4*)(Bp + 64 * ldb + k0);
        __syncthreads();
        As[lc + 0][lr] = a0.x; As[lc + 1][lr] = a0.y;
        As[lc + 2][lr] = a0.z; As[lc + 3][lr] = a0.w;
        As[lc + 0][lr + 64] = a1.x; As[lc + 1][lr + 64] = a1.y;
        As[lc + 2][lr + 64] = a1.z; As[lc + 3][lr + 64] = a1.w;
        Bs[lc + 0][lr] = b0.x; Bs[lc + 1][lr] = b0.y;
        Bs[lc + 2][lr] = b0.z; Bs[lc + 3][lr] = b0.w;
        Bs[lc + 0][lr + 64] = b1.x; Bs[lc + 1][lr + 64] = b1.y;
        Bs[lc + 2][lr + 64] = b1.z; Bs[lc + 3][lr + 64] = b1.w;
        __syncthreads();

        #pragma unroll
        for (int kk = 0; kk < 16; kk++) {
            float af[8], bf[8];
            *(float4*)(af)     = *(const float4*)&As[kk][ty * 4];
            *(float4*)(af + 4) = *(const float4*)&As[kk][64 + ty * 4];
            *(float4*)(bf)     = *(const float4*)&Bs[kk][tx * 4];
            *(float4*)(bf + 4) = *(const float4*)&Bs[kk][64 + tx * 4];
            #pragma unroll
            for (int i = 0; i < 8; i++)
                #pragma unroll
                for (int j = 0; j < 8; j++)
                    acc[i][j] += af[i] * bf[j];
        }
    }

    #pragma unroll
    for (int i = 0; i < 8; i++) {
        int r = bm + ((i < 4) ? (ty * 4 + i) : (64 + ty * 4 + (i - 4)));
        float* Cr = C + r * ldc + bn;
        *(float4*)(Cr + tx * 4)      = make_float4(acc[i][0], acc[i][1], acc[i][2], acc[i][3]);
        *(float4*)(Cr + 64 + tx * 4) = make_float4(acc[i][4], acc[i][5], acc[i][6], acc[i][7]);
    }
}

// ============================================================================
// RoPE (in-place on g_qkv): q heads 0..15 and k heads 16..19 are contiguous
// cols [0, 2560). tmp = concat(x[64:], x[:64]) with NO negation.
// ============================================================================
__global__ __launch_bounds__(256)
void rope_kernel(const float* __restrict__ cosb, const float* __restrict__ sinb)
{
    const int s = blockIdx.x;
    const float* cs = cosb + s * 128;
    const float* sn = sinb + s * 128;
    float* row = g_qkv + s * QKV_LD;
    for (int p = threadIdx.x; p < 20 * 64; p += 256) {
        const int head = p >> 6;       // 0..19 (16 q heads then 4 k heads)
        const int d = p & 63;          // 0..63
        float* base = row + head * 128;
        float x0 = base[d];
        float x1 = base[d + 64];
        base[d]      = x0 * cs[d]      + x1 * sn[d];
        base[d + 64] = x1 * cs[d + 64] + x0 * sn[d + 64];
    }
}

// ============================================================================
// Sliding-window flash attention, fp32.
// grid (16 heads, 64 q-blocks of 64), 256 threads.
// BQ=BK=64, HD=128; 4x4 S microtile, 4x8 O microtile per thread.
// ============================================================================
#define QK_PAD 129
#define V_PAD  132
#define P_PAD  65
#define ATTN_SMEM ((64 * QK_PAD * 2 + 64 * V_PAD + 64 * P_PAD) * 4)

__global__ __launch_bounds__(256)
void attn_kernel()
{
    extern __shared__ float smf[];
    float* Qs = smf;                       // 64 x 129
    float* Ks = Qs + 64 * QK_PAD;          // 64 x 129
    float* Vs = Ks + 64 * QK_PAD;          // 64 x 132
    float* Ps = Vs + 64 * V_PAD;           // 64 x 65

    const int h   = blockIdx.x;
    const int q0  = blockIdx.y * 64;
    const int kvh = h >> 2;
    const int tid = threadIdx.x;
    const int ty  = tid >> 4;              // 0..15
    const int tx  = tid & 15;              // 0..15

    // load Q tile (scaled by 1/sqrt(HD))
    for (int idx = tid; idx < 64 * 32; idx += 256) {
        int r = idx >> 5, c = (idx & 31) << 2;
        float4 v = *(const float4*)(g_qkv + (q0 + r) * QKV_LD + h * 128 + c);
        float* q = Qs + r * QK_PAD + c;
        q[0] = v.x * SCALE_F; q[1] = v.y * SCALE_F;
        q[2] = v.z * SCALE_F; q[3] = v.w * SCALE_F;
    }

    float m[4], l[4], acc[4][8];
    #pragma unroll
    for (int a = 0; a < 4; a++) {
        m[a] = -1e30f; l[a] = 0.f;
        #pragma unroll
        for (int c = 0; c < 8; c++) acc[a][c] = 0.f;
    }

    const int kstart = (q0 >= WIN_) ? (q0 - WIN_) : 0;

    for (int k0 = kstart; k0 <= q0; k0 += 64) {
        __syncthreads();   // prior PV done reading Vs
        // load K and V tiles
        for (int idx = tid; idx < 64 * 32; idx += 256) {
            int r = idx >> 5, c = (idx & 31) << 2;
            const float* src = g_qkv + (k0 + r) * QKV_LD + 2048 + kvh * 128 + c;
            float4 kv = *(const float4*)src;
            float* kd = Ks + r * QK_PAD + c;
            kd[0] = kv.x; kd[1] = kv.y; kd[2] = kv.z; kd[3] = kv.w;
            *(float4*)(Vs + r * V_PAD + c) = *(const float4*)(src + 512);
        }
        __syncthreads();

        // S = Q * K^T  (4x4 per thread)
        float s[4][4];
        #pragma unroll
        for (int a = 0; a < 4; a++)
            #pragma unroll
            for (int b = 0; b < 4; b++) s[a][b] = 0.f;

        #pragma unroll 4
        for (int d = 0; d < 128; d++) {
            float af[4], bf[4];
            #pragma unroll
            for (int a = 0; a < 4; a++) af[a] = Qs[(ty * 4 + a) * QK_PAD + d];
            #pragma unroll
            for (int b = 0; b < 4; b++) bf[b] = Ks[(tx * 4 + b) * QK_PAD + d];
            #pragma unroll
            for (int a = 0; a < 4; a++)
                #pragma unroll
                for (int b = 0; b < 4; b++)
                    s[a][b] += af[a] * bf[b];
        }

        // mask + online softmax
        #pragma unroll
        for (int a = 0; a < 4; a++) {
            const int i = q0 + ty * 4 + a;
            float rowmax = -1e30f;
            #pragma unroll
            for (int b = 0; b < 4; b++) {
                const int j = k0 + tx * 4 + b;
                const bool ok = (j <= i) && ((i - j) < WIN_);
                s[a][b] = ok ? s[a][b] : -1e30f;
                rowmax = fmaxf(rowmax, s[a][b]);
            }
            #pragma unroll
            for (int off = 8; off > 0; off >>= 1)
                rowmax = fmaxf(rowmax, __shfl_xor_sync(0xffffffffu, rowmax, off));
            const float mnew = fmaxf(m[a], rowmax);
            const float sc = __expf(m[a] - mnew);
            float rs = 0.f;
            #pragma unroll
            for (int b = 0; b < 4; b++) {
                float p = __expf(s[a][b] - mnew);
                Ps[(ty * 4 + a) * P_PAD + tx * 4 + b] = p;
                rs += p;
            }
            #pragma unroll
            for (int off = 8; off > 0; off >>= 1)
                rs += __shfl_xor_sync(0xffffffffu, rs, off);
            l[a] = l[a] * sc + rs;
            m[a] = mnew;
            #pragma unroll
            for (int c = 0; c < 8; c++) acc[a][c] *= sc;
        }
        __syncthreads();

        // O += P * V
        #pragma unroll 4
        for (int j = 0; j < 64; j++) {
            float p[4];
            #pragma unroll
            for (int a = 0; a < 4; a++) p[a] = Ps[(ty * 4 + a) * P_PAD + j];
            float4 v0 = *(const float4*)(Vs + j * V_PAD + tx * 8);
            float4 v1 = *(const float4*)(Vs + j * V_PAD + tx * 8 + 4);
            #pragma unroll
            for (int a = 0; a < 4; a++) {
                acc[a][0] += p[a] * v0.x; acc[a][1] += p[a] * v0.y;
                acc[a][2] += p[a] * v0.z; acc[a][3] += p[a] * v0.w;
                acc[a][4] += p[a] * v1.x; acc[a][5] += p[a] * v1.y;
                acc[a][6] += p[a] * v1.z; acc[a][7] += p[a] * v1.w;
            }
        }
    }

    // epilogue: normalize, write [s, h*128 + d]
    #pragma unroll
    for (int a = 0; a < 4; a++) {
        const float inv = 1.f / l[a];
        float* dst = g_attn + (q0 + ty * 4 + a) * HID + h * 128 + tx * 8;
        float4 o0 = make_float4(acc[a][0] * inv, acc[a][1] * inv, acc[a][2] * inv, acc[a][3] * inv);
        float4 o1 = make_float4(acc[a][4] * inv, acc[a][5] * inv, acc[a][6] * inv, acc[a][7] * inv);
        *(float4*)(dst)     = o0;
        *(float4*)(dst + 4) = o1;
    }
}

// ============================================================================
// Launch
// ============================================================================
extern "C" void kernel_launch(void* const* d_in, const int* in_sizes, int n_in,
                              void* d_out, int out_size)
{
    (void)in_sizes; (void)n_in; (void)out_size;
    const float* hidden = (const float*)d_in[0];
    const float* wq = (const float*)d_in[1];
    const float* wk = (const float*)d_in[2];
    const float* wv = (const float*)d_in[3];
    const float* wo = (const float*)d_in[4];
    const float* cosb = (const float*)d_in[5];
    const float* sinb = (const float*)d_in[6];
    float* out = (float*)d_out;

    void *qkvp, *attnp;
    cudaGetSymbolAddress(&qkvp, g_qkv);
    cudaGetSymbolAddress(&attnp, g_attn);
    float* qkv  = (float*)qkvp;
    float* attn = (float*)attnp;

    // QKV projections (C = A * W^T)
    gemm_abt<<<dim3(16, 32), 256>>>(hidden, HID, wq, HID, qkv,        QKV_LD, HID);
    gemm_abt<<<dim3( 4, 32), 256>>>(hidden, HID, wk, HID, qkv + 2048, QKV_LD, HID);
    gemm_abt<<<dim3( 4, 32), 256>>>(hidden, HID, wv, HID, qkv + 2560, QKV_LD, HID);

    // RoPE on q and k
    rope_kernel<<<S_LEN, 256>>>(cosb, sinb);

    // sliding-window attention
    cudaFuncSetAttribute(attn_kernel, cudaFuncAttributeMaxDynamicSharedMemorySize, ATTN_SMEM);
    attn_kernel<<<dim3(16, 64), 256, ATTN_SMEM>>>();

    // output projection
    gemm_abt<<<dim3(16, 32), 256>>>(attn, HID, wo, HID, out, HID, HID);
}